// round 16
// baseline (speedup 1.0000x reference)
#include <cuda_runtime.h>
#include <cuda_fp16.h>
#include <math.h>
#include <stdint.h>

// Problem constants
#define Bq 32
#define Sq 512
#define Hq 1024
#define NG 4096            // 4*H
#define Mq (Bq * Sq)       // 16384
#define HPAD 1032          // halves per smem h-tile row (1024 + 8)
#define FPHASES 513        // wavefront phases: L0 step p (p<=511), L1 step p-1 (p>=1)

// ---------------------------------------------------------------------------
// Scratch (device globals -- no allocations allowed)
// ---------------------------------------------------------------------------
static __device__ float g_Gx[(size_t)Mq * NG];             // layer-0 input-side gates
static __device__ float g_htf[2][Hq * Bq];                 // final h [layer][u*32+b]
static __device__ float g_cst[2][Hq * Bq];                 // final c [layer][u*32+b]
static __device__ volatile unsigned g_flags[128 * 32];     // distributed barrier (128B/flag)
static __device__ __half g_A16x[(size_t)Mq * 1024];        // x fp16 (GEMM A)
static __device__ __half g_W16h[(size_t)NG * 1024];        // GEMM Wx0 hi
static __device__ __half g_W16l[(size_t)NG * 1024];        // GEMM Wx0 lo
static __device__ __half g_F0[(size_t)NG * 1024];          // Wh0 fp16
static __device__ __half g_F1[(size_t)NG * 1024];          // Wh1 fp16
static __device__ __half g_X1[(size_t)NG * 1024];          // Wx1 fp16 (1-term)
static __device__ __half g_h0[2][Bq * 1024];               // layer-0 h exchange [parity][b][k]
static __device__ __half g_h1[2][Bq * 1024];               // layer-1 h exchange

// ---------------------------------------------------------------------------
// Base-ISA tensor helpers
// ---------------------------------------------------------------------------
__device__ __forceinline__ uint32_t smem_to_u32(const void* p) {
    uint32_t a;
    asm("{ .reg .u64 t; cvta.to.shared.u64 t, %1; cvt.u32.u64 %0, t; }" : "=r"(a) : "l"(p));
    return a;
}

#define LDSM_X4(r, addr) \
    asm volatile("ldmatrix.sync.aligned.m8n8.x4.shared.b16 {%0,%1,%2,%3}, [%4];" \
        : "=r"((r)[0]), "=r"((r)[1]), "=r"((r)[2]), "=r"((r)[3]) : "r"(addr))

#define MMA16816_FP(d, a, b0, b1) \
    asm volatile("mma.sync.aligned.m16n8k16.row.col.f32.f16.f16.f32 " \
        "{%0,%1,%2,%3}, {%4,%5,%6,%7}, {%8,%9}, {%0,%1,%2,%3};" \
        : "+f"((d)[0]), "+f"((d)[1]), "+f"((d)[2]), "+f"((d)[3]) \
        : "r"((a)[0]), "r"((a)[1]), "r"((a)[2]), "r"((a)[3]), "r"(b0), "r"(b1))

#define CP_ASYNC16(saddr, gptr) \
    asm volatile("cp.async.cg.shared.global [%0], [%1], 16;" :: "r"(saddr), "l"(gptr))
#define CP_COMMIT() asm volatile("cp.async.commit_group;" ::: "memory")
#define CP_WAIT(n)  asm volatile("cp.async.wait_group %0;" :: "n"(n) : "memory")
#define BAR_SYNC(id, cnt) asm volatile("bar.sync %0, %1;" :: "r"(id), "r"(cnt) : "memory")

// ---------------------------------------------------------------------------
// Zero fp16 h state + barrier flags
// ---------------------------------------------------------------------------
__global__ void k_zero_state() {
    int i = blockIdx.x * blockDim.x + threadIdx.x;
    int n = 2 * Bq * 1024 / 2;               // u32 per layer array (both parities)
    if (i < n) {
        ((uint32_t*)g_h0)[i] = 0u;
        ((uint32_t*)g_h1)[i] = 0u;
    }
    if (i < 128 * 32) g_flags[i] = 0u;
}

// ---------------------------------------------------------------------------
// fp32 -> fp16 single (rn)
// ---------------------------------------------------------------------------
__global__ void k_tof16(const float* __restrict__ src, __half* __restrict__ dst, int n4) {
    int i = blockIdx.x * blockDim.x + threadIdx.x;
    if (i >= n4) return;
    float4 v = ((const float4*)src)[i];
    ((__half2*)dst)[i * 2 + 0] = __halves2half2(__float2half_rn(v.x), __float2half_rn(v.y));
    ((__half2*)dst)[i * 2 + 1] = __halves2half2(__float2half_rn(v.z), __float2half_rn(v.w));
}

// ---------------------------------------------------------------------------
// fp32 -> fp16 (hi, lo) split (GEMM weights)
// ---------------------------------------------------------------------------
__global__ void k_split_f16(const float* __restrict__ src,
                            __half* __restrict__ hi,
                            __half* __restrict__ lo, int n4)
{
    int i = blockIdx.x * blockDim.x + threadIdx.x;
    if (i >= n4) return;
    float4 v = ((const float4*)src)[i];
    __half h0 = __float2half_rn(v.x), h1 = __float2half_rn(v.y);
    __half h2 = __float2half_rn(v.z), h3 = __float2half_rn(v.w);
    __half l0 = __float2half_rn(v.x - __half2float(h0));
    __half l1 = __float2half_rn(v.y - __half2float(h1));
    __half l2 = __float2half_rn(v.z - __half2float(h2));
    __half l3 = __float2half_rn(v.w - __half2float(h3));
    ((__half2*)hi)[i * 2 + 0] = __halves2half2(h0, h1);
    ((__half2*)hi)[i * 2 + 1] = __halves2half2(h2, h3);
    ((__half2*)lo)[i * 2 + 0] = __halves2half2(l0, l1);
    ((__half2*)lo)[i * 2 + 1] = __halves2half2(l2, l3);
}

// ---------------------------------------------------------------------------
// Tensor-core GEMM (fp16, 2-term):  g_Gx = A16x @ (W16h+W16l)^T   (layer 0)
// ---------------------------------------------------------------------------
#define GT_H   (128 * 72)
#define GBUF_BYTES (3 * GT_H * 2)
#define GSMEM_BYTES (2 * GBUF_BYTES)

__global__ __launch_bounds__(256, 1) void k_gemm_mma(const __half* __restrict__ A16)
{
    extern __shared__ __align__(16) char smem[];
    uint32_t sm_base = smem_to_u32(smem);
    int tid = threadIdx.x;
    int bn = blockIdx.x * 128;
    int bm = blockIdx.y * 128;
    int lane = tid & 31;
    int wid = tid >> 5;
    int wm = (wid & 1) * 64;
    int wn = (wid >> 1) * 32;

    const __half* gsrc[3];
    gsrc[0] = A16    + (size_t)bm * 1024;
    gsrc[1] = g_W16h + (size_t)bn * 1024;
    gsrc[2] = g_W16l + (size_t)bn * 1024;

    float acc[4][4][4];
#pragma unroll
    for (int i = 0; i < 4; i++)
#pragma unroll
        for (int j = 0; j < 4; j++)
#pragma unroll
            for (int k = 0; k < 4; k++) acc[i][j][k] = 0.f;

    int row_a = lane & 15;
    int kh_a  = lane >> 4;
    int row_b = (lane & 7) + ((lane >> 4) << 3);
    int kh_b  = (lane >> 3) & 1;

#define ISSUE_CHUNK(ch) do {                                                   \
    int _k0 = (ch) * 64;                                                       \
    uint32_t _sb = sm_base + ((ch) & 1) * GBUF_BYTES;                          \
    _Pragma("unroll")                                                          \
    for (int _r = 0; _r < 12; _r++) {                                          \
        int _id = tid + _r * 256;                                              \
        int _tile = _id >> 10;                                                 \
        int _row = (_id >> 3) & 127;                                           \
        int _k8 = (_id & 7) * 8;                                               \
        CP_ASYNC16(_sb + (uint32_t)(_tile * GT_H + _row * 72 + _k8) * 2,       \
                   gsrc[_tile] + (size_t)_row * 1024 + _k0 + _k8);             \
    }                                                                          \
    CP_COMMIT();                                                               \
} while (0)

    ISSUE_CHUNK(0);

    for (int ch = 0; ch < 16; ch++) {
        if (ch + 1 < 16) { ISSUE_CHUNK(ch + 1); CP_WAIT(1); }
        else             { CP_WAIT(0); }
        __syncthreads();

        uint32_t sb = sm_base + (ch & 1) * GBUF_BYTES;
        uint32_t a_t  = sb;
        uint32_t wh_t = sb + GT_H * 2;
        uint32_t wl_t = sb + 2 * GT_H * 2;

#pragma unroll
        for (int kk = 0; kk < 4; kk++) {
            uint32_t af[4][4], wh[2][4], wl[2][4];
#pragma unroll
            for (int mi = 0; mi < 4; mi++) {
                uint32_t off = (uint32_t)((wm + mi * 16 + row_a) * 72 + kk * 16 + kh_a * 8) * 2;
                LDSM_X4(af[mi], a_t + off);
            }
#pragma unroll
            for (int p = 0; p < 2; p++) {
                uint32_t off = (uint32_t)((wn + p * 16 + row_b) * 72 + kk * 16 + kh_b * 8) * 2;
                LDSM_X4(wh[p], wh_t + off);
                LDSM_X4(wl[p], wl_t + off);
            }
#pragma unroll
            for (int mi = 0; mi < 4; mi++)
#pragma unroll
                for (int ni = 0; ni < 4; ni++) {
                    int pr = ni >> 1, sb2 = (ni & 1) * 2;
                    MMA16816_FP(acc[mi][ni], af[mi], wh[pr][sb2], wh[pr][sb2 + 1]);
                    MMA16816_FP(acc[mi][ni], af[mi], wl[pr][sb2], wl[pr][sb2 + 1]);
                }
        }
        __syncthreads();
    }
#undef ISSUE_CHUNK

    int g = lane >> 2, tig = lane & 3;
#pragma unroll
    for (int mi = 0; mi < 4; mi++) {
#pragma unroll
        for (int ni = 0; ni < 4; ni++) {
            int row = bm + wm + mi * 16 + g;
            int col = bn + wn + ni * 8 + tig * 2;
            float2 v0 = make_float2(acc[mi][ni][0], acc[mi][ni][1]);
            float2 v1 = make_float2(acc[mi][ni][2], acc[mi][ni][3]);
            *(float2*)&g_Gx[(size_t)row * NG + col] = v0;
            *(float2*)&g_Gx[(size_t)(row + 8) * NG + col] = v1;
        }
    }
}

// ---------------------------------------------------------------------------
// Warp-specialized fused wavefront with chunked staging + DISTRIBUTED grid
// barrier (per-CTA flag lines; no atomic contention).
// 128 CTAs x 512 thr; CTA owns 8 L0-units AND 8 L1-units.
//   warps 0-7  (half A): Wh0@h0 -> bar.sync 1 -> L0 epilogue -> h0[p]
//   warps 8-15 (half B): Wx1@h0 + Wh1@h1 -> bar.sync 2 -> L1 epi -> h1[p-1]
// ---------------------------------------------------------------------------
#define SH0_OFF  0
#define SH1_OFF  66048                        // 32 x 1032 x 2
#define SWX_OFF  132096                       // + 66048
#define SP_OFF   (SWX_OFF + 65536)            // 197632 (32 rows x 2048B Wx1)
#define SP_STRIDE 34
#define SP_KS    (32 * SP_STRIDE)             // floats per k-slice (1088)
#define FSMEM_BYTES (SP_OFF + 8 * SP_KS * 4)  // 197632 + 34816 = 232448 (== cap)

__global__ __launch_bounds__(512, 1) void k_fused(
    const float* __restrict__ bx0, const float* __restrict__ bh0,
    const float* __restrict__ bx1, const float* __restrict__ bh1,
    float* __restrict__ dout)
{
    extern __shared__ __align__(16) char smem[];
    __half* sH0  = (__half*)(smem + SH0_OFF);
    float* sP    = (float*)(smem + SP_OFF);
    uint32_t smem_u = smem_to_u32(smem);
    uint32_t sH0_u = smem_u + SH0_OFF;
    uint32_t sH1_u = smem_u + SH1_OFF;

    int tid = threadIdx.x, lane = tid & 31, wid = tid >> 5;
    bool halfA = (wid < 8);
    int q  = halfA ? wid : (wid - 8);
    int mi = q & 1;                // 16-row half of the 32 gate rows
    int ks = q >> 1;               // 128-wide k slice within each 512-chunk
    int u0 = blockIdx.x * 8;       // 8 units per layer per CTA

    // kg -> k mapping (chunked)
    auto kg_to_k = [&](int kg) -> int {
        return (kg < 8) ? (ks * 128 + kg * 16) : (512 + ks * 128 + (kg - 8) * 16);
    };

    // ---- prologue: weight fragments (each warp holds ONE set of 16 frags) ----
    uint32_t a_w[16][4];
    {
        int r = tid >> 4, c16 = tid & 15;                   // staging: 32 rows
        int jrow = (r >> 3) * 1024 + u0 + (r & 7);
        int arow = mi * 16 + (lane & 15);
        int acol8 = (lane >> 4) * 8;
        uint32_t ab = sH0_u + (uint32_t)(arow * HPAD + acol8) * 2;

        const __half* wsrc = g_F0 + (size_t)jrow * 1024;
#pragma unroll
        for (int j = 0; j < 8; j++) {
            int cc = c16 + j * 16;
            *(uint4*)(sH0 + r * HPAD + cc * 8) = __ldcg((const uint4*)(wsrc + cc * 8));
        }
        __syncthreads();
        if (halfA) {
#pragma unroll
            for (int kg = 0; kg < 16; kg++)
                LDSM_X4(a_w[kg], ab + (uint32_t)(kg_to_k(kg) * 2));
        }
        __syncthreads();

        wsrc = g_F1 + (size_t)jrow * 1024;
#pragma unroll
        for (int j = 0; j < 8; j++) {
            int cc = c16 + j * 16;
            *(uint4*)(sH0 + r * HPAD + cc * 8) = __ldcg((const uint4*)(wsrc + cc * 8));
        }
        __syncthreads();
        if (!halfA) {
#pragma unroll
            for (int kg = 0; kg < 16; kg++)
                LDSM_X4(a_w[kg], ab + (uint32_t)(kg_to_k(kg) * 2));
        }
        __syncthreads();
    }

    // ---- prologue: Wx1 slice (32 rows x 1024) into permanent smem, swizzled ----
    {
        int lr = tid >> 4, c8 = (tid & 15) * 8;             // 32 rows, 16 thr/row
        int jrow = (lr >> 3) * 1024 + u0 + (lr & 7);
        uint32_t rxor = (uint32_t)((lr & 7) << 4);
#pragma unroll
        for (int j = 0; j < 8; j++) {
            int c = c8 + j * 128;
            uint4 v = __ldcg((const uint4*)(g_X1 + (size_t)jrow * 1024 + c));
            uint32_t off = (uint32_t)(lr * 2048) + (((uint32_t)(c * 2)) ^ rxor);
            *(uint4*)(smem + SWX_OFF + off) = v;
        }
    }

    // ---- epilogue ownership + register biases ----
    int et = halfA ? tid : (tid - 256);
    int eb = et >> 3, euu = et & 7;
    float br[4];
    {
#pragma unroll
        for (int g = 0; g < 4; g++) {
            int jrow = g * 1024 + u0 + euu;
            br[g] = halfA ? (bx0[jrow] + bh0[jrow]) : (bx1[jrow] + bh1[jrow]);
        }
    }
    __syncthreads();

    // ---- B-frag lane addressing (h tiles [32][HPAD]) ----
    int brow = ((lane >> 4) * 8) + (lane & 7);
    int bcol8 = ((lane >> 3) & 1) * 8;
    uint32_t b0h0 = sH0_u + (uint32_t)(brow * HPAD + bcol8) * 2;
    uint32_t b2h0 = b0h0 + (uint32_t)(16 * HPAD) * 2;
    uint32_t b0h1 = sH1_u + (uint32_t)(brow * HPAD + bcol8) * 2;
    uint32_t b2h1 = b0h1 + (uint32_t)(16 * HPAD) * 2;

    // Wx1 frag lane addressing (sWX, swizzled, row stride 2048B)
    int wrow = mi * 16 + (lane & 15);
    uint32_t wxbase = smem_u + SWX_OFF + (uint32_t)(wrow * 2048);
    uint32_t wxxor = (uint32_t)((wrow & 7) << 4);
    uint32_t wxlo = (uint32_t)((lane >> 4) * 8 * 2);

    int hb = tid >> 4, hc = tid & 15;
    float c_reg = 0.f;

    size_t gx_base = ((size_t)(eb * Sq)) * NG + u0 + euu;
    float gx[4];
    if (halfA) {
#pragma unroll
        for (int g = 0; g < 4; g++) gx[g] = __ldcg(&g_Gx[gx_base + (size_t)g * 1024]);
    }

    int pr16 = lane >> 2, pcolb = (lane & 3) * 2;
    float* sPmine = sP + (halfA ? 0 : 4 * SP_KS);

    for (int p = 0; p < FPHASES; p++) {
        // ---- staging as two chunked commit groups (k<512 then k>=512) ----
        {
            const __half* s0 = g_h0[p & 1] + hb * 1024;
            uint32_t d0 = sH0_u + (uint32_t)(hb * HPAD) * 2;
            const __half* s1 = g_h1[(p + 1) & 1] + hb * 1024;
            uint32_t d1 = sH1_u + (uint32_t)(hb * HPAD) * 2;
#pragma unroll
            for (int j = 0; j < 4; j++) {                  // chunk 0: k 0..511
                int cc = (hc + j * 16) * 8;
                CP_ASYNC16(d0 + (uint32_t)cc * 2, s0 + cc);
                if (p >= 1) CP_ASYNC16(d1 + (uint32_t)cc * 2, s1 + cc);
            }
            CP_COMMIT();
#pragma unroll
            for (int j = 4; j < 8; j++) {                  // chunk 1: k 512..1023
                int cc = (hc + j * 16) * 8;
                CP_ASYNC16(d0 + (uint32_t)cc * 2, s0 + cc);
                if (p >= 1) CP_ASYNC16(d1 + (uint32_t)cc * 2, s1 + cc);
            }
            CP_COMMIT();
        }

        float acc[4][4];
#pragma unroll
        for (int nf = 0; nf < 4; nf++)
#pragma unroll
            for (int e = 0; e < 4; e++) acc[nf][e] = 0.f;

        // ---- chunk 0 arrival -> MMA kg 0..7 (chunk 1 still in flight) ----
        CP_WAIT(1);
        __syncthreads();
        if (halfA) {
            if (p <= 511) {
#pragma unroll
                for (int kg = 0; kg < 8; kg++) {
                    uint32_t ko = (uint32_t)(kg_to_k(kg) * 2);
                    uint32_t bh[8];
                    LDSM_X4(&bh[0], b0h0 + ko);
                    LDSM_X4(&bh[4], b2h0 + ko);
#pragma unroll
                    for (int nf = 0; nf < 4; nf++)
                        MMA16816_FP(acc[nf], a_w[kg], bh[nf * 2], bh[nf * 2 + 1]);
                }
            }
        } else {
            if (p >= 1) {
#pragma unroll
                for (int kg = 0; kg < 8; kg++) {
                    int kx = kg_to_k(kg);
                    uint32_t ko = (uint32_t)(kx * 2);
                    uint32_t bh[8], wf[4];
                    LDSM_X4(&bh[0], b0h0 + ko);
                    LDSM_X4(&bh[4], b2h0 + ko);
                    LDSM_X4(wf, wxbase + (((uint32_t)(kx * 2) + wxlo) ^ wxxor));
#pragma unroll
                    for (int nf = 0; nf < 4; nf++)
                        MMA16816_FP(acc[nf], wf, bh[nf * 2], bh[nf * 2 + 1]);
                    LDSM_X4(&bh[0], b0h1 + ko);
                    LDSM_X4(&bh[4], b2h1 + ko);
#pragma unroll
                    for (int nf = 0; nf < 4; nf++)
                        MMA16816_FP(acc[nf], a_w[kg], bh[nf * 2], bh[nf * 2 + 1]);
                }
            }
        }

        // ---- chunk 1 arrival -> MMA kg 8..15 ----
        CP_WAIT(0);
        __syncthreads();
        if (halfA) {
            if (p <= 511) {
#pragma unroll
                for (int kg = 8; kg < 16; kg++) {
                    uint32_t ko = (uint32_t)(kg_to_k(kg) * 2);
                    uint32_t bh[8];
                    LDSM_X4(&bh[0], b0h0 + ko);
                    LDSM_X4(&bh[4], b2h0 + ko);
#pragma unroll
                    for (int nf = 0; nf < 4; nf++)
                        MMA16816_FP(acc[nf], a_w[kg], bh[nf * 2], bh[nf * 2 + 1]);
                }
                float* base = sPmine + ks * SP_KS + (mi * 16) * SP_STRIDE;
#pragma unroll
                for (int nf = 0; nf < 4; nf++) {
                    *(float2*)&base[(pr16)     * SP_STRIDE + nf * 8 + pcolb] = make_float2(acc[nf][0], acc[nf][1]);
                    *(float2*)&base[(pr16 + 8) * SP_STRIDE + nf * 8 + pcolb] = make_float2(acc[nf][2], acc[nf][3]);
                }
                BAR_SYNC(1, 256);

                // L0 epilogue
                int t = p;
                float gate[4];
#pragma unroll
                for (int g = 0; g < 4; g++) {
                    int row = g * 8 + euu;
                    float s = 0.f;
#pragma unroll
                    for (int kss = 0; kss < 4; kss++)
                        s += sP[kss * SP_KS + row * SP_STRIDE + eb];
                    gate[g] = s + br[g] + gx[g];
                }
                float sf = 1.f / (1.f + __expf(-gate[0]));
                float si = 1.f / (1.f + __expf(-gate[1]));
                float so = 1.f / (1.f + __expf(-gate[3]));
                float cn = sf * c_reg + si * tanhf(gate[2]);
                float hn = so * tanhf(cn);
                c_reg = cn;
                g_h0[(t + 1) & 1][eb * 1024 + u0 + euu] = __float2half_rn(hn);
                if (t == Sq - 1) {
                    int su = (u0 + euu) * Bq + eb;
                    g_htf[0][su] = hn; g_cst[0][su] = cn;
                }
                if (t + 1 < Sq) {
                    size_t gb = gx_base + (size_t)(t + 1) * NG;
#pragma unroll
                    for (int g = 0; g < 4; g++) gx[g] = __ldcg(&g_Gx[gb + (size_t)g * 1024]);
                }
            }
        } else {
            if (p >= 1) {
#pragma unroll
                for (int kg = 8; kg < 16; kg++) {
                    int kx = kg_to_k(kg);
                    uint32_t ko = (uint32_t)(kx * 2);
                    uint32_t bh[8], wf[4];
                    LDSM_X4(&bh[0], b0h0 + ko);
                    LDSM_X4(&bh[4], b2h0 + ko);
                    LDSM_X4(wf, wxbase + (((uint32_t)(kx * 2) + wxlo) ^ wxxor));
#pragma unroll
                    for (int nf = 0; nf < 4; nf++)
                        MMA16816_FP(acc[nf], wf, bh[nf * 2], bh[nf * 2 + 1]);
                    LDSM_X4(&bh[0], b0h1 + ko);
                    LDSM_X4(&bh[4], b2h1 + ko);
#pragma unroll
                    for (int nf = 0; nf < 4; nf++)
                        MMA16816_FP(acc[nf], a_w[kg], bh[nf * 2], bh[nf * 2 + 1]);
                }
                float* base = sPmine + ks * SP_KS + (mi * 16) * SP_STRIDE;
#pragma unroll
                for (int nf = 0; nf < 4; nf++) {
                    *(float2*)&base[(pr16)     * SP_STRIDE + nf * 8 + pcolb] = make_float2(acc[nf][0], acc[nf][1]);
                    *(float2*)&base[(pr16 + 8) * SP_STRIDE + nf * 8 + pcolb] = make_float2(acc[nf][2], acc[nf][3]);
                }
                BAR_SYNC(2, 256);

                // L1 epilogue
                int t = p - 1;
                float gate[4];
#pragma unroll
                for (int g = 0; g < 4; g++) {
                    int row = g * 8 + euu;
                    float s = 0.f;
#pragma unroll
                    for (int kss = 4; kss < 8; kss++)
                        s += sP[kss * SP_KS + row * SP_STRIDE + eb];
                    gate[g] = s + br[g];
                }
                float sf = 1.f / (1.f + __expf(-gate[0]));
                float si = 1.f / (1.f + __expf(-gate[1]));
                float so = 1.f / (1.f + __expf(-gate[3]));
                float cn = sf * c_reg + si * tanhf(gate[2]);
                float hn = so * tanhf(cn);
                c_reg = cn;
                dout[((size_t)(eb * Sq + t)) * Hq + u0 + euu] = hn;
                g_h1[(t + 1) & 1][eb * 1024 + u0 + euu] = __float2half_rn(hn);
                if (t == Sq - 1) {
                    int su = (u0 + euu) * Bq + eb;
                    g_htf[1][su] = hn; g_cst[1][su] = cn;
                }
            }
        }

        // ---- distributed grid barrier: one flag line per CTA ----
        __threadfence();
        __syncthreads();
        if (tid == 0) g_flags[blockIdx.x * 32] = (unsigned)(p + 1);
        if (tid < 128) {
            while (g_flags[tid * 32] < (unsigned)(p + 1)) { }
        }
        __syncthreads();
    }
}

// ---------------------------------------------------------------------------
// Tail: h_n [L,B,H] then c_n [L,B,H] after outputs.
// ---------------------------------------------------------------------------
__global__ void k_final(float* __restrict__ out) {
    int i = blockIdx.x * blockDim.x + threadIdx.x;
    int n = 2 * Bq * Hq;
    if (i < n) {
        int l = i / (Bq * Hq);
        int r = i - l * (Bq * Hq);
        int b = r / Hq;
        int u = r - b * Hq;
        out[(size_t)Mq * Hq + i]     = g_htf[l][u * Bq + b];
        out[(size_t)Mq * Hq + n + i] = g_cst[l][u * Bq + b];
    }
}

// ---------------------------------------------------------------------------
extern "C" void kernel_launch(void* const* d_in, const int* in_sizes, int n_in,
                              void* d_out, int out_size) {
    const float* x   = (const float*)d_in[0];
    const float* Wx0 = (const float*)d_in[1];
    const float* Wh0 = (const float*)d_in[2];
    const float* bx0 = (const float*)d_in[3];
    const float* bh0 = (const float*)d_in[4];
    const float* Wx1 = (const float*)d_in[5];
    const float* Wh1 = (const float*)d_in[6];
    const float* bx1 = (const float*)d_in[7];
    const float* bh1 = (const float*)d_in[8];
    float* out = (float*)d_out;

    cudaFuncSetAttribute(k_gemm_mma, cudaFuncAttributeMaxDynamicSharedMemorySize, GSMEM_BYTES);
    cudaFuncSetAttribute(k_fused,    cudaFuncAttributeMaxDynamicSharedMemorySize, FSMEM_BYTES);

    static __half *pA16x = nullptr, *pW16h = nullptr, *pW16l = nullptr;
    static __half *pF0 = nullptr, *pF1 = nullptr, *pX1 = nullptr;
    if (!pA16x) {
        cudaGetSymbolAddress((void**)&pA16x, g_A16x);
        cudaGetSymbolAddress((void**)&pW16h, g_W16h);
        cudaGetSymbolAddress((void**)&pW16l, g_W16l);
        cudaGetSymbolAddress((void**)&pF0,   g_F0);
        cudaGetSymbolAddress((void**)&pF1,   g_F1);
        cudaGetSymbolAddress((void**)&pX1,   g_X1);
    }

    const int nZ = 2 * Bq * 1024 / 2;
    k_zero_state<<<(nZ + 255) / 256, 256>>>();

    const int nA4 = Mq * 1024 / 4;
    const int nW4 = NG * 1024 / 4;
    dim3 ggrid(NG / 128, Mq / 128);      // (32, 128)

    // Layer-0 input GEMM operands + GEMM
    k_tof16<<<(nA4 + 255) / 256, 256>>>(x, pA16x, nA4);
    k_split_f16<<<(nW4 + 255) / 256, 256>>>(Wx0, pW16h, pW16l, nW4);
    k_gemm_mma<<<ggrid, 256, GSMEM_BYTES>>>(pA16x);

    // Recurrent weights fp16
    k_tof16<<<(nW4 + 255) / 256, 256>>>(Wh0, pF0, nW4);
    k_tof16<<<(nW4 + 255) / 256, 256>>>(Wh1, pF1, nW4);
    k_tof16<<<(nW4 + 255) / 256, 256>>>(Wx1, pX1, nW4);

    // Warp-specialized fused wavefront with distributed barrier
    k_fused<<<128, 512, FSMEM_BYTES>>>(bx0, bh0, bx1, bh1, out);

    // Tail
    if (out_size >= Mq * Hq + 4 * Bq * Hq)
        k_final<<<(2 * Bq * Hq + 255) / 256, 256>>>(out);
}

// round 17
// speedup vs baseline: 1.0736x; 1.0736x over previous
#include <cuda_runtime.h>
#include <cuda_fp16.h>
#include <math.h>
#include <stdint.h>

// Problem constants
#define Bq 32
#define Sq 512
#define Hq 1024
#define NG 4096            // 4*H
#define Mq (Bq * Sq)       // 16384
#define HPAD 1032          // halves per smem h-tile row (1024 + 8)
#define FPHASES 513        // wavefront phases: L0 step p (p<=511), L1 step p-1 (p>=1)

// ---------------------------------------------------------------------------
// Scratch (device globals -- no allocations allowed)
// ---------------------------------------------------------------------------
static __device__ float g_Gx[(size_t)Mq * NG];             // layer-0 input-side gates
static __device__ float g_htf[2][Hq * Bq];                 // final h [layer][u*32+b]
static __device__ float g_cst[2][Hq * Bq];                 // final c [layer][u*32+b]
static __device__ unsigned g_bar[1];                       // grid barrier counter
static __device__ __half g_A16x[(size_t)Mq * 1024];        // x fp16 (GEMM A)
static __device__ __half g_W16h[(size_t)NG * 1024];        // GEMM Wx0 hi
static __device__ __half g_W16l[(size_t)NG * 1024];        // GEMM Wx0 lo
static __device__ __half g_F0[(size_t)NG * 1024];          // Wh0 fp16
static __device__ __half g_F1[(size_t)NG * 1024];          // Wh1 fp16
static __device__ __half g_X1[(size_t)NG * 1024];          // Wx1 fp16 (1-term)
static __device__ __half g_h0[2][Bq * 1024];               // layer-0 h exchange [parity][b][k]
static __device__ __half g_h1[2][Bq * 1024];               // layer-1 h exchange

// ---------------------------------------------------------------------------
// Base-ISA tensor helpers
// ---------------------------------------------------------------------------
__device__ __forceinline__ uint32_t smem_to_u32(const void* p) {
    uint32_t a;
    asm("{ .reg .u64 t; cvta.to.shared.u64 t, %1; cvt.u32.u64 %0, t; }" : "=r"(a) : "l"(p));
    return a;
}

#define LDSM_X4(r, addr) \
    asm volatile("ldmatrix.sync.aligned.m8n8.x4.shared.b16 {%0,%1,%2,%3}, [%4];" \
        : "=r"((r)[0]), "=r"((r)[1]), "=r"((r)[2]), "=r"((r)[3]) : "r"(addr))

#define MMA16816_FP(d, a, b0, b1) \
    asm volatile("mma.sync.aligned.m16n8k16.row.col.f32.f16.f16.f32 " \
        "{%0,%1,%2,%3}, {%4,%5,%6,%7}, {%8,%9}, {%0,%1,%2,%3};" \
        : "+f"((d)[0]), "+f"((d)[1]), "+f"((d)[2]), "+f"((d)[3]) \
        : "r"((a)[0]), "r"((a)[1]), "r"((a)[2]), "r"((a)[3]), "r"(b0), "r"(b1))

#define CP_ASYNC16(saddr, gptr) \
    asm volatile("cp.async.cg.shared.global [%0], [%1], 16;" :: "r"(saddr), "l"(gptr))
#define CP_COMMIT() asm volatile("cp.async.commit_group;" ::: "memory")
#define CP_WAIT(n)  asm volatile("cp.async.wait_group %0;" :: "n"(n) : "memory")
#define BAR_SYNC(id, cnt) asm volatile("bar.sync %0, %1;" :: "r"(id), "r"(cnt) : "memory")

// ---------------------------------------------------------------------------
// Zero fp16 h state + barrier counter
// ---------------------------------------------------------------------------
__global__ void k_zero_state() {
    int i = blockIdx.x * blockDim.x + threadIdx.x;
    int n = 2 * Bq * 1024 / 2;               // u32 per layer array (both parities)
    if (i < n) {
        ((uint32_t*)g_h0)[i] = 0u;
        ((uint32_t*)g_h1)[i] = 0u;
    }
    if (i == 0) g_bar[0] = 0u;
}

// ---------------------------------------------------------------------------
// fp32 -> fp16 single (rn)
// ---------------------------------------------------------------------------
__global__ void k_tof16(const float* __restrict__ src, __half* __restrict__ dst, int n4) {
    int i = blockIdx.x * blockDim.x + threadIdx.x;
    if (i >= n4) return;
    float4 v = ((const float4*)src)[i];
    ((__half2*)dst)[i * 2 + 0] = __halves2half2(__float2half_rn(v.x), __float2half_rn(v.y));
    ((__half2*)dst)[i * 2 + 1] = __halves2half2(__float2half_rn(v.z), __float2half_rn(v.w));
}

// ---------------------------------------------------------------------------
// fp32 -> fp16 (hi, lo) split (GEMM weights)
// ---------------------------------------------------------------------------
__global__ void k_split_f16(const float* __restrict__ src,
                            __half* __restrict__ hi,
                            __half* __restrict__ lo, int n4)
{
    int i = blockIdx.x * blockDim.x + threadIdx.x;
    if (i >= n4) return;
    float4 v = ((const float4*)src)[i];
    __half h0 = __float2half_rn(v.x), h1 = __float2half_rn(v.y);
    __half h2 = __float2half_rn(v.z), h3 = __float2half_rn(v.w);
    __half l0 = __float2half_rn(v.x - __half2float(h0));
    __half l1 = __float2half_rn(v.y - __half2float(h1));
    __half l2 = __float2half_rn(v.z - __half2float(h2));
    __half l3 = __float2half_rn(v.w - __half2float(h3));
    ((__half2*)hi)[i * 2 + 0] = __halves2half2(h0, h1);
    ((__half2*)hi)[i * 2 + 1] = __halves2half2(h2, h3);
    ((__half2*)lo)[i * 2 + 0] = __halves2half2(l0, l1);
    ((__half2*)lo)[i * 2 + 1] = __halves2half2(l2, l3);
}

// ---------------------------------------------------------------------------
// Tensor-core GEMM (fp16, 2-term):  g_Gx = A16x @ (W16h+W16l)^T   (layer 0)
// __launch_bounds__(256, 2): cap regs at 128 so TWO CTAs fit per SM
// (smem 2x110592 = 221184 <= 228KB) -> latency hiding across syncs.
// ---------------------------------------------------------------------------
#define GT_H   (128 * 72)
#define GBUF_BYTES (3 * GT_H * 2)
#define GSMEM_BYTES (2 * GBUF_BYTES)

__global__ __launch_bounds__(256, 2) void k_gemm_mma(const __half* __restrict__ A16)
{
    extern __shared__ __align__(16) char smem[];
    uint32_t sm_base = smem_to_u32(smem);
    int tid = threadIdx.x;
    int bn = blockIdx.x * 128;
    int bm = blockIdx.y * 128;
    int lane = tid & 31;
    int wid = tid >> 5;
    int wm = (wid & 1) * 64;
    int wn = (wid >> 1) * 32;

    const __half* gsrc[3];
    gsrc[0] = A16    + (size_t)bm * 1024;
    gsrc[1] = g_W16h + (size_t)bn * 1024;
    gsrc[2] = g_W16l + (size_t)bn * 1024;

    float acc[4][4][4];
#pragma unroll
    for (int i = 0; i < 4; i++)
#pragma unroll
        for (int j = 0; j < 4; j++)
#pragma unroll
            for (int k = 0; k < 4; k++) acc[i][j][k] = 0.f;

    int row_a = lane & 15;
    int kh_a  = lane >> 4;
    int row_b = (lane & 7) + ((lane >> 4) << 3);
    int kh_b  = (lane >> 3) & 1;

#define ISSUE_CHUNK(ch) do {                                                   \
    int _k0 = (ch) * 64;                                                       \
    uint32_t _sb = sm_base + ((ch) & 1) * GBUF_BYTES;                          \
    _Pragma("unroll")                                                          \
    for (int _r = 0; _r < 12; _r++) {                                          \
        int _id = tid + _r * 256;                                              \
        int _tile = _id >> 10;                                                 \
        int _row = (_id >> 3) & 127;                                           \
        int _k8 = (_id & 7) * 8;                                               \
        CP_ASYNC16(_sb + (uint32_t)(_tile * GT_H + _row * 72 + _k8) * 2,       \
                   gsrc[_tile] + (size_t)_row * 1024 + _k0 + _k8);             \
    }                                                                          \
    CP_COMMIT();                                                               \
} while (0)

    ISSUE_CHUNK(0);

    for (int ch = 0; ch < 16; ch++) {
        if (ch + 1 < 16) { ISSUE_CHUNK(ch + 1); CP_WAIT(1); }
        else             { CP_WAIT(0); }
        __syncthreads();

        uint32_t sb = sm_base + (ch & 1) * GBUF_BYTES;
        uint32_t a_t  = sb;
        uint32_t wh_t = sb + GT_H * 2;
        uint32_t wl_t = sb + 2 * GT_H * 2;

#pragma unroll
        for (int kk = 0; kk < 4; kk++) {
            uint32_t af[4][4], wh[2][4], wl[2][4];
#pragma unroll
            for (int mi = 0; mi < 4; mi++) {
                uint32_t off = (uint32_t)((wm + mi * 16 + row_a) * 72 + kk * 16 + kh_a * 8) * 2;
                LDSM_X4(af[mi], a_t + off);
            }
#pragma unroll
            for (int p = 0; p < 2; p++) {
                uint32_t off = (uint32_t)((wn + p * 16 + row_b) * 72 + kk * 16 + kh_b * 8) * 2;
                LDSM_X4(wh[p], wh_t + off);
                LDSM_X4(wl[p], wl_t + off);
            }
#pragma unroll
            for (int mi = 0; mi < 4; mi++)
#pragma unroll
                for (int ni = 0; ni < 4; ni++) {
                    int pr = ni >> 1, sb2 = (ni & 1) * 2;
                    MMA16816_FP(acc[mi][ni], af[mi], wh[pr][sb2], wh[pr][sb2 + 1]);
                    MMA16816_FP(acc[mi][ni], af[mi], wl[pr][sb2], wl[pr][sb2 + 1]);
                }
        }
        __syncthreads();
    }
#undef ISSUE_CHUNK

    int g = lane >> 2, tig = lane & 3;
#pragma unroll
    for (int mi = 0; mi < 4; mi++) {
#pragma unroll
        for (int ni = 0; ni < 4; ni++) {
            int row = bm + wm + mi * 16 + g;
            int col = bn + wn + ni * 8 + tig * 2;
            float2 v0 = make_float2(acc[mi][ni][0], acc[mi][ni][1]);
            float2 v1 = make_float2(acc[mi][ni][2], acc[mi][ni][3]);
            *(float2*)&g_Gx[(size_t)row * NG + col] = v0;
            *(float2*)&g_Gx[(size_t)(row + 8) * NG + col] = v1;
        }
    }
}

// ---------------------------------------------------------------------------
// Warp-specialized fused wavefront with chunked staging + centralized atomic
// grid barrier (distributed flags regressed in R16; atomic is faster).
// 128 CTAs x 512 thr; CTA owns 8 L0-units AND 8 L1-units.
//   warps 0-7  (half A): Wh0@h0 -> bar.sync 1 -> L0 epilogue -> h0[p]
//   warps 8-15 (half B): Wx1@h0 + Wh1@h1 -> bar.sync 2 -> L1 epi -> h1[p-1]
// ---------------------------------------------------------------------------
#define SH0_OFF  0
#define SH1_OFF  66048                        // 32 x 1032 x 2
#define SWX_OFF  132096                       // + 66048
#define SP_OFF   (SWX_OFF + 65536)            // 197632 (32 rows x 2048B Wx1)
#define SP_STRIDE 34
#define SP_KS    (32 * SP_STRIDE)             // floats per k-slice (1088)
#define FSMEM_BYTES (SP_OFF + 8 * SP_KS * 4)  // 197632 + 34816 = 232448 (== cap)

__global__ __launch_bounds__(512, 1) void k_fused(
    const float* __restrict__ bx0, const float* __restrict__ bh0,
    const float* __restrict__ bx1, const float* __restrict__ bh1,
    float* __restrict__ dout)
{
    extern __shared__ __align__(16) char smem[];
    __half* sH0  = (__half*)(smem + SH0_OFF);
    float* sP    = (float*)(smem + SP_OFF);
    uint32_t smem_u = smem_to_u32(smem);
    uint32_t sH0_u = smem_u + SH0_OFF;
    uint32_t sH1_u = smem_u + SH1_OFF;

    int tid = threadIdx.x, lane = tid & 31, wid = tid >> 5;
    bool halfA = (wid < 8);
    int q  = halfA ? wid : (wid - 8);
    int mi = q & 1;                // 16-row half of the 32 gate rows
    int ks = q >> 1;               // 128-wide k slice within each 512-chunk
    int u0 = blockIdx.x * 8;       // 8 units per layer per CTA

    // kg -> k mapping (chunked)
    auto kg_to_k = [&](int kg) -> int {
        return (kg < 8) ? (ks * 128 + kg * 16) : (512 + ks * 128 + (kg - 8) * 16);
    };

    // ---- prologue: weight fragments (each warp holds ONE set of 16 frags) ----
    uint32_t a_w[16][4];
    {
        int r = tid >> 4, c16 = tid & 15;                   // staging: 32 rows
        int jrow = (r >> 3) * 1024 + u0 + (r & 7);
        int arow = mi * 16 + (lane & 15);
        int acol8 = (lane >> 4) * 8;
        uint32_t ab = sH0_u + (uint32_t)(arow * HPAD + acol8) * 2;

        const __half* wsrc = g_F0 + (size_t)jrow * 1024;
#pragma unroll
        for (int j = 0; j < 8; j++) {
            int cc = c16 + j * 16;
            *(uint4*)(sH0 + r * HPAD + cc * 8) = __ldcg((const uint4*)(wsrc + cc * 8));
        }
        __syncthreads();
        if (halfA) {
#pragma unroll
            for (int kg = 0; kg < 16; kg++)
                LDSM_X4(a_w[kg], ab + (uint32_t)(kg_to_k(kg) * 2));
        }
        __syncthreads();

        wsrc = g_F1 + (size_t)jrow * 1024;
#pragma unroll
        for (int j = 0; j < 8; j++) {
            int cc = c16 + j * 16;
            *(uint4*)(sH0 + r * HPAD + cc * 8) = __ldcg((const uint4*)(wsrc + cc * 8));
        }
        __syncthreads();
        if (!halfA) {
#pragma unroll
            for (int kg = 0; kg < 16; kg++)
                LDSM_X4(a_w[kg], ab + (uint32_t)(kg_to_k(kg) * 2));
        }
        __syncthreads();
    }

    // ---- prologue: Wx1 slice (32 rows x 1024) into permanent smem, swizzled ----
    {
        int lr = tid >> 4, c8 = (tid & 15) * 8;             // 32 rows, 16 thr/row
        int jrow = (lr >> 3) * 1024 + u0 + (lr & 7);
        uint32_t rxor = (uint32_t)((lr & 7) << 4);
#pragma unroll
        for (int j = 0; j < 8; j++) {
            int c = c8 + j * 128;
            uint4 v = __ldcg((const uint4*)(g_X1 + (size_t)jrow * 1024 + c));
            uint32_t off = (uint32_t)(lr * 2048) + (((uint32_t)(c * 2)) ^ rxor);
            *(uint4*)(smem + SWX_OFF + off) = v;
        }
    }

    // ---- epilogue ownership + register biases ----
    int et = halfA ? tid : (tid - 256);
    int eb = et >> 3, euu = et & 7;
    float br[4];
    {
#pragma unroll
        for (int g = 0; g < 4; g++) {
            int jrow = g * 1024 + u0 + euu;
            br[g] = halfA ? (bx0[jrow] + bh0[jrow]) : (bx1[jrow] + bh1[jrow]);
        }
    }
    __syncthreads();

    // ---- B-frag lane addressing (h tiles [32][HPAD]) ----
    int brow = ((lane >> 4) * 8) + (lane & 7);
    int bcol8 = ((lane >> 3) & 1) * 8;
    uint32_t b0h0 = sH0_u + (uint32_t)(brow * HPAD + bcol8) * 2;
    uint32_t b2h0 = b0h0 + (uint32_t)(16 * HPAD) * 2;
    uint32_t b0h1 = sH1_u + (uint32_t)(brow * HPAD + bcol8) * 2;
    uint32_t b2h1 = b0h1 + (uint32_t)(16 * HPAD) * 2;

    // Wx1 frag lane addressing (sWX, swizzled, row stride 2048B)
    int wrow = mi * 16 + (lane & 15);
    uint32_t wxbase = smem_u + SWX_OFF + (uint32_t)(wrow * 2048);
    uint32_t wxxor = (uint32_t)((wrow & 7) << 4);
    uint32_t wxlo = (uint32_t)((lane >> 4) * 8 * 2);

    int hb = tid >> 4, hc = tid & 15;
    float c_reg = 0.f;

    size_t gx_base = ((size_t)(eb * Sq)) * NG + u0 + euu;
    float gx[4];
    if (halfA) {
#pragma unroll
        for (int g = 0; g < 4; g++) gx[g] = __ldcg(&g_Gx[gx_base + (size_t)g * 1024]);
    }

    int pr16 = lane >> 2, pcolb = (lane & 3) * 2;
    float* sPmine = sP + (halfA ? 0 : 4 * SP_KS);

    for (int p = 0; p < FPHASES; p++) {
        // ---- staging as two chunked commit groups (k<512 then k>=512) ----
        {
            const __half* s0 = g_h0[p & 1] + hb * 1024;
            uint32_t d0 = sH0_u + (uint32_t)(hb * HPAD) * 2;
            const __half* s1 = g_h1[(p + 1) & 1] + hb * 1024;
            uint32_t d1 = sH1_u + (uint32_t)(hb * HPAD) * 2;
#pragma unroll
            for (int j = 0; j < 4; j++) {                  // chunk 0: k 0..511
                int cc = (hc + j * 16) * 8;
                CP_ASYNC16(d0 + (uint32_t)cc * 2, s0 + cc);
                if (p >= 1) CP_ASYNC16(d1 + (uint32_t)cc * 2, s1 + cc);
            }
            CP_COMMIT();
#pragma unroll
            for (int j = 4; j < 8; j++) {                  // chunk 1: k 512..1023
                int cc = (hc + j * 16) * 8;
                CP_ASYNC16(d0 + (uint32_t)cc * 2, s0 + cc);
                if (p >= 1) CP_ASYNC16(d1 + (uint32_t)cc * 2, s1 + cc);
            }
            CP_COMMIT();
        }

        float acc[4][4];
#pragma unroll
        for (int nf = 0; nf < 4; nf++)
#pragma unroll
            for (int e = 0; e < 4; e++) acc[nf][e] = 0.f;

        // ---- chunk 0 arrival -> MMA kg 0..7 (chunk 1 still in flight) ----
        CP_WAIT(1);
        __syncthreads();
        if (halfA) {
            if (p <= 511) {
#pragma unroll
                for (int kg = 0; kg < 8; kg++) {
                    uint32_t ko = (uint32_t)(kg_to_k(kg) * 2);
                    uint32_t bh[8];
                    LDSM_X4(&bh[0], b0h0 + ko);
                    LDSM_X4(&bh[4], b2h0 + ko);
#pragma unroll
                    for (int nf = 0; nf < 4; nf++)
                        MMA16816_FP(acc[nf], a_w[kg], bh[nf * 2], bh[nf * 2 + 1]);
                }
            }
        } else {
            if (p >= 1) {
#pragma unroll
                for (int kg = 0; kg < 8; kg++) {
                    int kx = kg_to_k(kg);
                    uint32_t ko = (uint32_t)(kx * 2);
                    uint32_t bh[8], wf[4];
                    LDSM_X4(&bh[0], b0h0 + ko);
                    LDSM_X4(&bh[4], b2h0 + ko);
                    LDSM_X4(wf, wxbase + (((uint32_t)(kx * 2) + wxlo) ^ wxxor));
#pragma unroll
                    for (int nf = 0; nf < 4; nf++)
                        MMA16816_FP(acc[nf], wf, bh[nf * 2], bh[nf * 2 + 1]);
                    LDSM_X4(&bh[0], b0h1 + ko);
                    LDSM_X4(&bh[4], b2h1 + ko);
#pragma unroll
                    for (int nf = 0; nf < 4; nf++)
                        MMA16816_FP(acc[nf], a_w[kg], bh[nf * 2], bh[nf * 2 + 1]);
                }
            }
        }

        // ---- chunk 1 arrival -> MMA kg 8..15 ----
        CP_WAIT(0);
        __syncthreads();
        if (halfA) {
            if (p <= 511) {
#pragma unroll
                for (int kg = 8; kg < 16; kg++) {
                    uint32_t ko = (uint32_t)(kg_to_k(kg) * 2);
                    uint32_t bh[8];
                    LDSM_X4(&bh[0], b0h0 + ko);
                    LDSM_X4(&bh[4], b2h0 + ko);
#pragma unroll
                    for (int nf = 0; nf < 4; nf++)
                        MMA16816_FP(acc[nf], a_w[kg], bh[nf * 2], bh[nf * 2 + 1]);
                }
                float* base = sPmine + ks * SP_KS + (mi * 16) * SP_STRIDE;
#pragma unroll
                for (int nf = 0; nf < 4; nf++) {
                    *(float2*)&base[(pr16)     * SP_STRIDE + nf * 8 + pcolb] = make_float2(acc[nf][0], acc[nf][1]);
                    *(float2*)&base[(pr16 + 8) * SP_STRIDE + nf * 8 + pcolb] = make_float2(acc[nf][2], acc[nf][3]);
                }
                BAR_SYNC(1, 256);

                // L0 epilogue
                int t = p;
                float gate[4];
#pragma unroll
                for (int g = 0; g < 4; g++) {
                    int row = g * 8 + euu;
                    float s = 0.f;
#pragma unroll
                    for (int kss = 0; kss < 4; kss++)
                        s += sP[kss * SP_KS + row * SP_STRIDE + eb];
                    gate[g] = s + br[g] + gx[g];
                }
                float sf = 1.f / (1.f + __expf(-gate[0]));
                float si = 1.f / (1.f + __expf(-gate[1]));
                float so = 1.f / (1.f + __expf(-gate[3]));
                float cn = sf * c_reg + si * tanhf(gate[2]);
                float hn = so * tanhf(cn);
                c_reg = cn;
                g_h0[(t + 1) & 1][eb * 1024 + u0 + euu] = __float2half_rn(hn);
                if (t == Sq - 1) {
                    int su = (u0 + euu) * Bq + eb;
                    g_htf[0][su] = hn; g_cst[0][su] = cn;
                }
                if (t + 1 < Sq) {
                    size_t gb = gx_base + (size_t)(t + 1) * NG;
#pragma unroll
                    for (int g = 0; g < 4; g++) gx[g] = __ldcg(&g_Gx[gb + (size_t)g * 1024]);
                }
            }
        } else {
            if (p >= 1) {
#pragma unroll
                for (int kg = 8; kg < 16; kg++) {
                    int kx = kg_to_k(kg);
                    uint32_t ko = (uint32_t)(kx * 2);
                    uint32_t bh[8], wf[4];
                    LDSM_X4(&bh[0], b0h0 + ko);
                    LDSM_X4(&bh[4], b2h0 + ko);
                    LDSM_X4(wf, wxbase + (((uint32_t)(kx * 2) + wxlo) ^ wxxor));
#pragma unroll
                    for (int nf = 0; nf < 4; nf++)
                        MMA16816_FP(acc[nf], wf, bh[nf * 2], bh[nf * 2 + 1]);
                    LDSM_X4(&bh[0], b0h1 + ko);
                    LDSM_X4(&bh[4], b2h1 + ko);
#pragma unroll
                    for (int nf = 0; nf < 4; nf++)
                        MMA16816_FP(acc[nf], a_w[kg], bh[nf * 2], bh[nf * 2 + 1]);
                }
                float* base = sPmine + ks * SP_KS + (mi * 16) * SP_STRIDE;
#pragma unroll
                for (int nf = 0; nf < 4; nf++) {
                    *(float2*)&base[(pr16)     * SP_STRIDE + nf * 8 + pcolb] = make_float2(acc[nf][0], acc[nf][1]);
                    *(float2*)&base[(pr16 + 8) * SP_STRIDE + nf * 8 + pcolb] = make_float2(acc[nf][2], acc[nf][3]);
                }
                BAR_SYNC(2, 256);

                // L1 epilogue
                int t = p - 1;
                float gate[4];
#pragma unroll
                for (int g = 0; g < 4; g++) {
                    int row = g * 8 + euu;
                    float s = 0.f;
#pragma unroll
                    for (int kss = 4; kss < 8; kss++)
                        s += sP[kss * SP_KS + row * SP_STRIDE + eb];
                    gate[g] = s + br[g];
                }
                float sf = 1.f / (1.f + __expf(-gate[0]));
                float si = 1.f / (1.f + __expf(-gate[1]));
                float so = 1.f / (1.f + __expf(-gate[3]));
                float cn = sf * c_reg + si * tanhf(gate[2]);
                float hn = so * tanhf(cn);
                c_reg = cn;
                dout[((size_t)(eb * Sq + t)) * Hq + u0 + euu] = hn;
                g_h1[(t + 1) & 1][eb * 1024 + u0 + euu] = __float2half_rn(hn);
                if (t == Sq - 1) {
                    int su = (u0 + euu) * Bq + eb;
                    g_htf[1][su] = hn; g_cst[1][su] = cn;
                }
            }
        }

        // ---- grid barrier (centralized atomic; fastest variant measured) ----
        __threadfence();
        __syncthreads();
        if (tid == 0) {
            atomicAdd(&g_bar[0], 1u);
            unsigned target = 128u * (unsigned)(p + 1);
            while (*(volatile unsigned*)&g_bar[0] < target) { }
        }
        __syncthreads();
    }
}

// ---------------------------------------------------------------------------
// Tail: h_n [L,B,H] then c_n [L,B,H] after outputs.
// ---------------------------------------------------------------------------
__global__ void k_final(float* __restrict__ out) {
    int i = blockIdx.x * blockDim.x + threadIdx.x;
    int n = 2 * Bq * Hq;
    if (i < n) {
        int l = i / (Bq * Hq);
        int r = i - l * (Bq * Hq);
        int b = r / Hq;
        int u = r - b * Hq;
        out[(size_t)Mq * Hq + i]     = g_htf[l][u * Bq + b];
        out[(size_t)Mq * Hq + n + i] = g_cst[l][u * Bq + b];
    }
}

// ---------------------------------------------------------------------------
extern "C" void kernel_launch(void* const* d_in, const int* in_sizes, int n_in,
                              void* d_out, int out_size) {
    const float* x   = (const float*)d_in[0];
    const float* Wx0 = (const float*)d_in[1];
    const float* Wh0 = (const float*)d_in[2];
    const float* bx0 = (const float*)d_in[3];
    const float* bh0 = (const float*)d_in[4];
    const float* Wx1 = (const float*)d_in[5];
    const float* Wh1 = (const float*)d_in[6];
    const float* bx1 = (const float*)d_in[7];
    const float* bh1 = (const float*)d_in[8];
    float* out = (float*)d_out;

    cudaFuncSetAttribute(k_gemm_mma, cudaFuncAttributeMaxDynamicSharedMemorySize, GSMEM_BYTES);
    cudaFuncSetAttribute(k_fused,    cudaFuncAttributeMaxDynamicSharedMemorySize, FSMEM_BYTES);

    static __half *pA16x = nullptr, *pW16h = nullptr, *pW16l = nullptr;
    static __half *pF0 = nullptr, *pF1 = nullptr, *pX1 = nullptr;
    if (!pA16x) {
        cudaGetSymbolAddress((void**)&pA16x, g_A16x);
        cudaGetSymbolAddress((void**)&pW16h, g_W16h);
        cudaGetSymbolAddress((void**)&pW16l, g_W16l);
        cudaGetSymbolAddress((void**)&pF0,   g_F0);
        cudaGetSymbolAddress((void**)&pF1,   g_F1);
        cudaGetSymbolAddress((void**)&pX1,   g_X1);
    }

    const int nZ = 2 * Bq * 1024 / 2;
    k_zero_state<<<(nZ + 255) / 256, 256>>>();

    const int nA4 = Mq * 1024 / 4;
    const int nW4 = NG * 1024 / 4;
    dim3 ggrid(NG / 128, Mq / 128);      // (32, 128)

    // Layer-0 input GEMM operands + GEMM (now 2 CTAs/SM)
    k_tof16<<<(nA4 + 255) / 256, 256>>>(x, pA16x, nA4);
    k_split_f16<<<(nW4 + 255) / 256, 256>>>(Wx0, pW16h, pW16l, nW4);
    k_gemm_mma<<<ggrid, 256, GSMEM_BYTES>>>(pA16x);

    // Recurrent weights fp16
    k_tof16<<<(nW4 + 255) / 256, 256>>>(Wh0, pF0, nW4);
    k_tof16<<<(nW4 + 255) / 256, 256>>>(Wh1, pF1, nW4);
    k_tof16<<<(nW4 + 255) / 256, 256>>>(Wx1, pX1, nW4);

    // Warp-specialized fused wavefront (atomic barrier restored)
    k_fused<<<128, 512, FSMEM_BYTES>>>(bx0, bh0, bx1, bh1, out);

    // Tail
    if (out_size >= Mq * Hq + 4 * Bq * Hq)
        k_final<<<(2 * Bq * Hq + 255) / 256, 256>>>(out);
}